// round 2
// baseline (speedup 1.0000x reference)
#include <cuda_runtime.h>
#include <math.h>

#define BB 4
#define AA 4096
#define DD 128
#define TOKENS (BB*AA)

// scratch (no cudaMalloc allowed)
__device__ float g_Q[(size_t)TOKENS*DD];
__device__ float g_K[(size_t)TOKENS*DD];
__device__ float g_V[(size_t)TOKENS*DD];
__device__ float g_H[(size_t)TOKENS*DD];

__device__ __forceinline__ float swishf(float x) {
    return x / (1.0f + __expf(-x));
}

// ---------------- QKV projection: [16384,128] @ [128,128] x3 ----------------
__global__ __launch_bounds__(256, 1) void qkv_kernel(
    const float* __restrict__ x,
    const float* __restrict__ Wq,
    const float* __restrict__ Wk,
    const float* __restrict__ Wv)
{
    extern __shared__ float sm[];
    float* xs = sm;            // 128 x 132 (padded)
    float* ws = sm + 128*132;  // 128 x 128
    const int tid = threadIdx.x;
    const int tx = tid & 15, ty = tid >> 4;
    const int tok0 = blockIdx.x * 128;

    for (int i = tid; i < 128*32; i += 256) {
        int r = i >> 5, c = (i & 31) << 2;
        *(float4*)&xs[r*132 + c] = *(const float4*)&x[(size_t)(tok0 + r)*DD + c];
    }

    for (int w = 0; w < 3; w++) {
        const float* W = (w == 0) ? Wq : (w == 1) ? Wk : Wv;
        float* outp = (w == 0) ? g_Q : (w == 1) ? g_K : g_V;
        __syncthreads();
        for (int i = tid; i < 128*32; i += 256) {
            int r = i >> 5, c = (i & 31) << 2;
            *(float4*)&ws[r*128 + c] = *(const float4*)&W[r*DD + c];
        }
        __syncthreads();
        float acc[8][8];
        #pragma unroll
        for (int i = 0; i < 8; i++)
            #pragma unroll
            for (int j = 0; j < 8; j++) acc[i][j] = 0.f;

        for (int kk = 0; kk < 128; kk++) {
            float xv[8], wv[8];
            #pragma unroll
            for (int i = 0; i < 8; i++) xv[i] = xs[(ty*8+i)*132 + kk];
            #pragma unroll
            for (int j = 0; j < 4; j++) {
                wv[j]   = ws[kk*128 + tx*4 + j];
                wv[4+j] = ws[kk*128 + 64 + tx*4 + j];
            }
            #pragma unroll
            for (int i = 0; i < 8; i++)
                #pragma unroll
                for (int j = 0; j < 8; j++) acc[i][j] += xv[i]*wv[j];
        }
        #pragma unroll
        for (int i = 0; i < 8; i++) {
            size_t t = (size_t)(tok0 + ty*8 + i)*DD;
            *(float4*)&outp[t + tx*4]      = make_float4(acc[i][0],acc[i][1],acc[i][2],acc[i][3]);
            *(float4*)&outp[t + 64 + tx*4] = make_float4(acc[i][4],acc[i][5],acc[i][6],acc[i][7]);
        }
    }
}

// ---------------- flash attention w/ additive connectivity bias ----------------
// BM=128 queries per CTA, BN=64 keys per tile. grid (32,4) = 128 CTAs (1 wave).
__global__ __launch_bounds__(256, 1) void attn_kernel(const float* __restrict__ conn)
{
    extern __shared__ float sm[];
    float* Qs = sm;                  // 128*132
    float* Ks = Qs + 128*132;        // 64*132
    float* Vs = Ks + 64*132;         // 64*128
    float* Ps = Vs + 64*128;         // 128*64
    const int b = blockIdx.y;
    const int q0 = blockIdx.x * 128;
    const int tid = threadIdx.x;
    const int tx = tid & 15, ty = tid >> 4;

    const float* Qg = g_Q + (size_t)b*AA*DD;
    const float* Kg = g_K + (size_t)b*AA*DD;
    const float* Vg = g_V + (size_t)b*AA*DD;

    for (int i = tid; i < 128*32; i += 256) {
        int r = i >> 5, c = (i & 31) << 2;
        *(float4*)&Qs[r*132 + c] = *(const float4*)&Qg[(size_t)(q0 + r)*DD + c];
    }

    float m[8], l[8], O[8][8];
    #pragma unroll
    for (int i = 0; i < 8; i++) {
        m[i] = -1e30f; l[i] = 0.f;
        #pragma unroll
        for (int j = 0; j < 8; j++) O[i][j] = 0.f;
    }

    const float inv_scale = 0.08838834764831845f; // 1/sqrt(128)

    for (int k0 = 0; k0 < AA; k0 += 64) {
        __syncthreads();
        for (int i = tid; i < 64*32; i += 256) {
            int r = i >> 5, c = (i & 31) << 2;
            *(float4*)&Ks[r*132 + c] = *(const float4*)&Kg[(size_t)(k0 + r)*DD + c];
            *(float4*)&Vs[r*128 + c] = *(const float4*)&Vg[(size_t)(k0 + r)*DD + c];
        }
        __syncthreads();

        // S[128x64] = Q tile . K tile^T  (rows 8ty+i, cols 4tx+j)
        float S[8][4];
        #pragma unroll
        for (int i = 0; i < 8; i++) { S[i][0]=0.f; S[i][1]=0.f; S[i][2]=0.f; S[i][3]=0.f; }

        for (int kk = 0; kk < 128; kk += 4) {
            float qv[8][4];
            #pragma unroll
            for (int i = 0; i < 8; i++) {
                float4 t = *(const float4*)&Qs[(ty*8+i)*132 + kk];
                qv[i][0]=t.x; qv[i][1]=t.y; qv[i][2]=t.z; qv[i][3]=t.w;
            }
            #pragma unroll
            for (int u = 0; u < 4; u++) {
                float kv[4];
                #pragma unroll
                for (int j = 0; j < 4; j++) kv[j] = Ks[(tx*4+j)*132 + kk + u];
                #pragma unroll
                for (int i = 0; i < 8; i++)
                    #pragma unroll
                    for (int j = 0; j < 4; j++) S[i][j] += qv[i][u]*kv[j];
            }
        }

        // scale + connectivity bias + online softmax
        #pragma unroll
        for (int i = 0; i < 8; i++) {
            float4 cv = *(const float4*)&conn[((size_t)b*AA + (size_t)(q0 + ty*8 + i))*AA + k0 + tx*4];
            float s0 = S[i][0]*inv_scale + cv.x;
            float s1 = S[i][1]*inv_scale + cv.y;
            float s2 = S[i][2]*inv_scale + cv.z;
            float s3 = S[i][3]*inv_scale + cv.w;
            float mx = fmaxf(fmaxf(s0,s1), fmaxf(s2,s3));
            #pragma unroll
            for (int o = 8; o; o >>= 1) mx = fmaxf(mx, __shfl_xor_sync(0xffffffffu, mx, o));
            float mn = fmaxf(m[i], mx);
            float sc = __expf(m[i] - mn);
            float p0 = __expf(s0 - mn), p1 = __expf(s1 - mn);
            float p2 = __expf(s2 - mn), p3 = __expf(s3 - mn);
            *(float4*)&Ps[(ty*8+i)*64 + tx*4] = make_float4(p0,p1,p2,p3);
            float rs = p0+p1+p2+p3;
            #pragma unroll
            for (int o = 8; o; o >>= 1) rs += __shfl_xor_sync(0xffffffffu, rs, o);
            l[i] = l[i]*sc + rs;
            m[i] = mn;
            #pragma unroll
            for (int j = 0; j < 8; j++) O[i][j] *= sc;
        }
        __syncwarp();

        // O += P . V   (O cols: {4tx..4tx+3} and {64+4tx..64+4tx+3})
        for (int kk = 0; kk < 64; kk += 4) {
            float pv[8][4];
            #pragma unroll
            for (int i = 0; i < 8; i++) {
                float4 t = *(const float4*)&Ps[(ty*8+i)*64 + kk];
                pv[i][0]=t.x; pv[i][1]=t.y; pv[i][2]=t.z; pv[i][3]=t.w;
            }
            #pragma unroll
            for (int u = 0; u < 4; u++) {
                float4 v0 = *(const float4*)&Vs[(kk+u)*128 + tx*4];
                float4 v1 = *(const float4*)&Vs[(kk+u)*128 + 64 + tx*4];
                #pragma unroll
                for (int i = 0; i < 8; i++) {
                    O[i][0] += pv[i][u]*v0.x;
                    O[i][1] += pv[i][u]*v0.y;
                    O[i][2] += pv[i][u]*v0.z;
                    O[i][3] += pv[i][u]*v0.w;
                    O[i][4] += pv[i][u]*v1.x;
                    O[i][5] += pv[i][u]*v1.y;
                    O[i][6] += pv[i][u]*v1.z;
                    O[i][7] += pv[i][u]*v1.w;
                }
            }
        }
        __syncwarp();
    }

    float* Hg = g_H + (size_t)b*AA*DD;
    #pragma unroll
    for (int i = 0; i < 8; i++) {
        float inv = 1.0f / l[i];
        size_t base = (size_t)(q0 + ty*8 + i)*DD;
        *(float4*)&Hg[base + tx*4]      = make_float4(O[i][0]*inv, O[i][1]*inv, O[i][2]*inv, O[i][3]*inv);
        *(float4*)&Hg[base + 64 + tx*4] = make_float4(O[i][4]*inv, O[i][5]*inv, O[i][6]*inv, O[i][7]*inv);
    }
}

// ---------------- swish -> W1 -> swish -> W2 -> LayerNorm ----------------
__global__ __launch_bounds__(256, 1) void mlp_kernel(
    const float* __restrict__ W1, const float* __restrict__ b1,
    const float* __restrict__ W2, const float* __restrict__ b2,
    const float* __restrict__ gamma, const float* __restrict__ beta,
    float* __restrict__ out)
{
    extern __shared__ float sm[];
    float* hs  = sm;              // 128*132
    float* hs2 = hs + 128*132;    // 128*132
    float* ws  = hs2 + 128*132;   // 128*128
    const int tid = threadIdx.x;
    const int tx = tid & 15, ty = tid >> 4;
    const int tok0 = blockIdx.x * 128;

    for (int i = tid; i < 128*32; i += 256) {
        int r = i >> 5, c = (i & 31) << 2;
        float4 v = *(const float4*)&g_H[(size_t)(tok0 + r)*DD + c];
        v.x = swishf(v.x); v.y = swishf(v.y); v.z = swishf(v.z); v.w = swishf(v.w);
        *(float4*)&hs[r*132 + c] = v;
        *(float4*)&ws[r*128 + c] = *(const float4*)&W1[r*DD + c];
    }
    __syncthreads();

    float acc[8][8];
    #pragma unroll
    for (int j = 0; j < 4; j++) {
        float bA = b1[tx*4 + j], bB = b1[64 + tx*4 + j];
        #pragma unroll
        for (int i = 0; i < 8; i++) { acc[i][j] = bA; acc[i][4+j] = bB; }
    }
    for (int kk = 0; kk < 128; kk++) {
        float xv[8], wv[8];
        #pragma unroll
        for (int i = 0; i < 8; i++) xv[i] = hs[(ty*8+i)*132 + kk];
        #pragma unroll
        for (int j = 0; j < 4; j++) {
            wv[j]   = ws[kk*128 + tx*4 + j];
            wv[4+j] = ws[kk*128 + 64 + tx*4 + j];
        }
        #pragma unroll
        for (int i = 0; i < 8; i++)
            #pragma unroll
            for (int j = 0; j < 8; j++) acc[i][j] += xv[i]*wv[j];
    }
    __syncthreads();   // everyone done with ws(W1) & hs

    #pragma unroll
    for (int i = 0; i < 8; i++) {
        *(float4*)&hs2[(ty*8+i)*132 + tx*4] =
            make_float4(swishf(acc[i][0]),swishf(acc[i][1]),swishf(acc[i][2]),swishf(acc[i][3]));
        *(float4*)&hs2[(ty*8+i)*132 + 64 + tx*4] =
            make_float4(swishf(acc[i][4]),swishf(acc[i][5]),swishf(acc[i][6]),swishf(acc[i][7]));
    }
    for (int i = tid; i < 128*32; i += 256) {
        int r = i >> 5, c = (i & 31) << 2;
        *(float4*)&ws[r*128 + c] = *(const float4*)&W2[r*DD + c];
    }
    __syncthreads();

    #pragma unroll
    for (int j = 0; j < 4; j++) {
        float bA = b2[tx*4 + j], bB = b2[64 + tx*4 + j];
        #pragma unroll
        for (int i = 0; i < 8; i++) { acc[i][j] = bA; acc[i][4+j] = bB; }
    }
    for (int kk = 0; kk < 128; kk++) {
        float xv[8], wv[8];
        #pragma unroll
        for (int i = 0; i < 8; i++) xv[i] = hs2[(ty*8+i)*132 + kk];
        #pragma unroll
        for (int j = 0; j < 4; j++) {
            wv[j]   = ws[kk*128 + tx*4 + j];
            wv[4+j] = ws[kk*128 + 64 + tx*4 + j];
        }
        #pragma unroll
        for (int i = 0; i < 8; i++)
            #pragma unroll
            for (int j = 0; j < 8; j++) acc[i][j] += xv[i]*wv[j];
    }

    float gm[8], bt[8];
    #pragma unroll
    for (int j = 0; j < 4; j++) {
        gm[j]   = gamma[tx*4+j]; gm[4+j] = gamma[64+tx*4+j];
        bt[j]   = beta[tx*4+j];  bt[4+j] = beta[64+tx*4+j];
    }
    #pragma unroll
    for (int i = 0; i < 8; i++) {
        float s1 = 0.f, s2 = 0.f;
        #pragma unroll
        for (int j = 0; j < 8; j++) { s1 += acc[i][j]; s2 += acc[i][j]*acc[i][j]; }
        #pragma unroll
        for (int o = 8; o; o >>= 1) {
            s1 += __shfl_xor_sync(0xffffffffu, s1, o);
            s2 += __shfl_xor_sync(0xffffffffu, s2, o);
        }
        float mu  = s1 * (1.0f/128.0f);
        float var = s2 * (1.0f/128.0f) - mu*mu;
        float rstd = rsqrtf(var + 1e-5f);
        size_t base = (size_t)(tok0 + ty*8 + i)*DD;
        float4 o0, o1;
        o0.x = (acc[i][0]-mu)*rstd*gm[0] + bt[0];
        o0.y = (acc[i][1]-mu)*rstd*gm[1] + bt[1];
        o0.z = (acc[i][2]-mu)*rstd*gm[2] + bt[2];
        o0.w = (acc[i][3]-mu)*rstd*gm[3] + bt[3];
        o1.x = (acc[i][4]-mu)*rstd*gm[4] + bt[4];
        o1.y = (acc[i][5]-mu)*rstd*gm[5] + bt[5];
        o1.z = (acc[i][6]-mu)*rstd*gm[6] + bt[6];
        o1.w = (acc[i][7]-mu)*rstd*gm[7] + bt[7];
        *(float4*)&out[base + tx*4]      = o0;
        *(float4*)&out[base + 64 + tx*4] = o1;
    }
}

extern "C" void kernel_launch(void* const* d_in, const int* in_sizes, int n_in,
                              void* d_out, int out_size)
{
    const float* x     = (const float*)d_in[0];
    const float* conn  = (const float*)d_in[1];
    const float* Wq    = (const float*)d_in[2];
    const float* Wk    = (const float*)d_in[3];
    const float* Wv    = (const float*)d_in[4];
    const float* W1    = (const float*)d_in[5];
    const float* b1    = (const float*)d_in[6];
    const float* W2    = (const float*)d_in[7];
    const float* b2    = (const float*)d_in[8];
    const float* gamma = (const float*)d_in[9];
    const float* beta  = (const float*)d_in[10];
    float* out = (float*)d_out;

    const size_t smem_qkv  = (size_t)(128*132 + 128*128) * sizeof(float);              // 133120
    const size_t smem_attn = (size_t)(128*132 + 64*132 + 64*128 + 128*64) * sizeof(float); // 166912
    const size_t smem_mlp  = (size_t)(128*132*2 + 128*128) * sizeof(float);            // 200704

    cudaFuncSetAttribute(qkv_kernel,  cudaFuncAttributeMaxDynamicSharedMemorySize, (int)smem_qkv);
    cudaFuncSetAttribute(attn_kernel, cudaFuncAttributeMaxDynamicSharedMemorySize, (int)smem_attn);
    cudaFuncSetAttribute(mlp_kernel,  cudaFuncAttributeMaxDynamicSharedMemorySize, (int)smem_mlp);

    qkv_kernel<<<128, 256, smem_qkv>>>(x, Wq, Wk, Wv);
    attn_kernel<<<dim3(32, 4), 256, smem_attn>>>(conn);
    mlp_kernel<<<128, 256, smem_mlp>>>(W1, b1, W2, b2, gamma, beta, out);
}